// round 1
// baseline (speedup 1.0000x reference)
#include <cuda_runtime.h>

// VanillaRNN step on GB300 — Round 0 baseline.
//
// Problem shapes: B=8192, D_IN=1024, H=4096, D_OUT=1024 (all fp32).
//   new_state = ReLU(X @ W_in^T + b_in + state @ W_rec^T + b_rec)   [B,H]
//   out       = ReLU(new_state @ W_out^T + b_out)                   [B,D_OUT]
// Output buffer = flattened tuple (out, new_state):
//   d_out[0 .. B*D_OUT)            <- out
//   d_out[B*D_OUT .. B*(D_OUT+H))  <- new_state  (also reused as GEMM3 input)
//
// Kernel: generic C = ReLU(A1@B1^T + A2@B2^T + bias1 + bias2), NT layout
// (A row-major [M,K], B row-major [N,K], K contiguous in both).
// 128x128 tile, KT=16, 256 threads, 8x8 micro-tile per thread.

#define MT 128
#define NT_ 128
#define KT 16
#define PAD 4

__global__ __launch_bounds__(256, 1)
void gemm_nt_bias_relu(
    const float* __restrict__ A1, int K1,
    const float* __restrict__ B1,
    const float* __restrict__ A2, int K2,
    const float* __restrict__ B2,
    const float* __restrict__ bias1,
    const float* __restrict__ bias2,
    float* __restrict__ C, int ldc)
{
    __shared__ float As[KT][MT + PAD];
    __shared__ float Bs[KT][NT_ + PAD];

    const int tid = threadIdx.x;
    const int rowBase = blockIdx.y * MT;
    const int colBase = blockIdx.x * NT_;
    const int tm = (tid >> 4) * 8;   // 0..120, m offset within tile
    const int tn = (tid & 15) * 8;   // 0..120, n offset within tile

    float acc[8][8];
#pragma unroll
    for (int i = 0; i < 8; i++)
#pragma unroll
        for (int j = 0; j < 8; j++) acc[i][j] = 0.0f;

#pragma unroll 1
    for (int phase = 0; phase < 2; ++phase) {
        const float* A = phase ? A2 : A1;
        const float* B = phase ? B2 : B1;
        const int K   = phase ? K2 : K1;
        if (K == 0) continue;

#pragma unroll 1
        for (int k0 = 0; k0 < K; k0 += KT) {
            // ---- load A tile [MT x KT] and B tile [NT x KT], store transposed ----
#pragma unroll
            for (int i = 0; i < 2; i++) {
                const int idx = tid + i * 256;      // 0..511
                const int r   = idx >> 2;           // 0..127 (row within tile)
                const int c4  = (idx & 3) * 4;      // 0,4,8,12 (k offset)
                const float4 va = *(const float4*)&A[(size_t)(rowBase + r) * K + k0 + c4];
                As[c4 + 0][r] = va.x;
                As[c4 + 1][r] = va.y;
                As[c4 + 2][r] = va.z;
                As[c4 + 3][r] = va.w;
                const float4 vb = *(const float4*)&B[(size_t)(colBase + r) * K + k0 + c4];
                Bs[c4 + 0][r] = vb.x;
                Bs[c4 + 1][r] = vb.y;
                Bs[c4 + 2][r] = vb.z;
                Bs[c4 + 3][r] = vb.w;
            }
            __syncthreads();

            // ---- compute ----
#pragma unroll
            for (int k = 0; k < KT; k++) {
                float a[8], b[8];
#pragma unroll
                for (int i = 0; i < 8; i++) a[i] = As[k][tm + i];
#pragma unroll
                for (int j = 0; j < 8; j++) b[j] = Bs[k][tn + j];
#pragma unroll
                for (int i = 0; i < 8; i++)
#pragma unroll
                    for (int j = 0; j < 8; j++)
                        acc[i][j] = fmaf(a[i], b[j], acc[i][j]);
            }
            __syncthreads();
        }
    }

    // ---- epilogue: bias + ReLU, vectorized store ----
    float bsum[8];
#pragma unroll
    for (int j = 0; j < 8; j++) {
        float bv = bias1[colBase + tn + j];
        if (bias2) bv += bias2[colBase + tn + j];
        bsum[j] = bv;
    }
#pragma unroll
    for (int i = 0; i < 8; i++) {
        const int row = rowBase + tm + i;
        float4 v0, v1;
        v0.x = fmaxf(acc[i][0] + bsum[0], 0.0f);
        v0.y = fmaxf(acc[i][1] + bsum[1], 0.0f);
        v0.z = fmaxf(acc[i][2] + bsum[2], 0.0f);
        v0.w = fmaxf(acc[i][3] + bsum[3], 0.0f);
        v1.x = fmaxf(acc[i][4] + bsum[4], 0.0f);
        v1.y = fmaxf(acc[i][5] + bsum[5], 0.0f);
        v1.z = fmaxf(acc[i][6] + bsum[6], 0.0f);
        v1.w = fmaxf(acc[i][7] + bsum[7], 0.0f);
        *(float4*)&C[(size_t)row * ldc + colBase + tn + 0] = v0;
        *(float4*)&C[(size_t)row * ldc + colBase + tn + 4] = v1;
    }
}

extern "C" void kernel_launch(void* const* d_in, const int* in_sizes, int n_in,
                              void* d_out, int out_size)
{
    (void)in_sizes; (void)n_in; (void)out_size;

    const int B_   = 8192;
    const int D_IN = 1024;
    const int H_   = 4096;
    const int D_O  = 1024;

    const float* X     = (const float*)d_in[0];
    const float* state = (const float*)d_in[1];
    const float* W_in  = (const float*)d_in[2];
    const float* b_in  = (const float*)d_in[3];
    const float* W_rec = (const float*)d_in[4];
    const float* b_rec = (const float*)d_in[5];
    const float* W_out = (const float*)d_in[6];
    const float* b_out = (const float*)d_in[7];

    float* out       = (float*)d_out;                      // [B, D_OUT]
    float* new_state = (float*)d_out + (size_t)B_ * D_O;   // [B, H]

    // GEMM1+2 fused: new_state = ReLU(X@W_in^T + state@W_rec^T + b_in + b_rec)
    {
        dim3 grid(H_ / NT_, B_ / MT);
        gemm_nt_bias_relu<<<grid, 256>>>(
            X, D_IN, W_in,
            state, H_, W_rec,
            b_in, b_rec,
            new_state, H_);
    }

    // GEMM3: out = ReLU(new_state@W_out^T + b_out)
    {
        dim3 grid(D_O / NT_, B_ / MT);
        gemm_nt_bias_relu<<<grid, 256>>>(
            new_state, H_, W_out,
            nullptr, 0, nullptr,
            b_out, nullptr,
            out, D_O);
    }
}

// round 6
// speedup vs baseline: 2.0618x; 2.0618x over previous
#include <cuda_runtime.h>
#include <cstdint>

// VanillaRNN on GB300 — Round 2: warp-level tf32 mma.sync (base compute_103
// has no tcgen05/'a'-suffix features), cp.async 3-stage pipeline.
//
//   new_state = ReLU(X@W_in^T + state@W_rec^T + b_in + b_rec)  [8192,4096]
//   out       = ReLU(new_state@W_out^T + b_out)                [8192,1024]
// d_out = (out, new_state); new_state region reused as GEMM3 input.
//
// BM=BN=128, BK=32, 128 threads (4 warps, 2x2), warp tile 64x64,
// mma m16n8k8 tf32 (4x8 tiles/warp), 128 f32 acc/thread.
// SMEM rows padded to 36 floats: fragment LDS banks = 4*g + tg (conflict-free),
// and 16B cp.async needs no transpose. Inputs rounded to tf32-RN via +0x1000.

#define BM 128
#define BN 128
#define BK 32
#define STAGES 3
#define SROW 36                         // floats per smem row (32 + 4 pad)
#define TILE_FLOATS (BM * SROW)         // 4608 per operand
#define STAGE_FLOATS (2 * TILE_FLOATS)  // 9216
#define STAGE_BYTES  (STAGE_FLOATS * 4) // 36864
#define SMEM_BYTES   (STAGES * STAGE_BYTES) // 110592

__device__ __forceinline__ uint32_t s2u(const void* p) {
    uint32_t a;
    asm("{ .reg .u64 t; cvta.to.shared.u64 t, %1; cvt.u32.u64 %0, t; }" : "=r"(a) : "l"(p));
    return a;
}

#define CP16(dst, src) \
    asm volatile("cp.async.cg.shared.global [%0], [%1], 16;" :: "r"(dst), "l"(src))
#define CP_COMMIT() asm volatile("cp.async.commit_group;" ::: "memory")
#define CP_WAIT(N)  asm volatile("cp.async.wait_group %0;" :: "n"(N) : "memory")

// round fp32 bits to tf32 nearest: +half-ulp(13-bit) then HW truncation
__device__ __forceinline__ uint32_t rnd(float f) { return __float_as_uint(f) + 0x1000u; }

#define MMA_TF32(ac, a0, a1, a2, a3, b0, b1)                                   \
    asm volatile(                                                              \
        "mma.sync.aligned.m16n8k8.row.col.f32.tf32.tf32.f32 "                  \
        "{%0,%1,%2,%3}, {%4,%5,%6,%7}, {%8,%9}, {%0,%1,%2,%3};"                \
        : "+f"((ac)[0]), "+f"((ac)[1]), "+f"((ac)[2]), "+f"((ac)[3])           \
        : "r"(a0), "r"(a1), "r"(a2), "r"(a3), "r"(b0), "r"(b1))

__global__ void __launch_bounds__(128, 2) rnn_gemm_mma(
    const float* __restrict__ A1, int lda1,
    const float* __restrict__ B1, int ldb1, int n1,
    const float* __restrict__ A2, int lda2,
    const float* __restrict__ B2, int ldb2, int n2,
    const float* __restrict__ bias1, const float* __restrict__ bias2,
    float* __restrict__ C, int ldc)
{
    extern __shared__ __align__(16) float smem[];
    const uint32_t sbase = s2u(smem);

    const int tid  = threadIdx.x;
    const int warp = tid >> 5;
    const int lane = tid & 31;
    const int g    = lane >> 2;   // group id (0..7)
    const int tg   = lane & 3;    // thread in group (0..3)
    const int wm   = warp >> 1;   // warp m index (0..1)
    const int wn   = warp & 1;    // warp n index (0..1)

    const int rowBase = blockIdx.y * BM;
    const int colBase = blockIdx.x * BN;
    const int niters  = n1 + n2;

    float acc[4][8][4];
#pragma unroll
    for (int i = 0; i < 4; i++)
#pragma unroll
        for (int j = 0; j < 8; j++)
#pragma unroll
            for (int v = 0; v < 4; v++) acc[i][j][v] = 0.0f;

    // ---- stage loader: each thread fills one A row + one B row (8x16B each)
    auto load_stage = [&](int j, int s) {
        const float* Ab; const float* Bb; int lda, ldb, ko;
        if (j < n1) { Ab = A1; Bb = B1; lda = lda1; ldb = ldb1; ko = j * BK; }
        else        { Ab = A2; Bb = B2; lda = lda2; ldb = ldb2; ko = (j - n1) * BK; }
        const uint32_t stA = sbase + s * STAGE_BYTES + tid * (SROW * 4);
        const uint32_t stB = stA + TILE_FLOATS * 4;
        const float* ga = Ab + (size_t)(rowBase + tid) * lda + ko;
        const float* gb = Bb + (size_t)(colBase + tid) * ldb + ko;
#pragma unroll
        for (int c = 0; c < 8; c++) CP16(stA + c * 16, ga + c * 4);
#pragma unroll
        for (int c = 0; c < 8; c++) CP16(stB + c * 16, gb + c * 4);
    };

    // ---- prologue: 2 stages in flight ----
    load_stage(0, 0); CP_COMMIT();
    load_stage(1, 1); CP_COMMIT();

    // ---- main loop ----
#pragma unroll 1
    for (int it = 0; it < niters; ++it) {
        const int s = it % STAGES;
        if (it < niters - 1) { CP_WAIT(1); } else { CP_WAIT(0); }
        __syncthreads();

        if (it + 2 < niters) { load_stage(it + 2, (it + 2) % STAGES); CP_COMMIT(); }

        const float* sA = smem + s * STAGE_FLOATS;
        const float* sB = sA + TILE_FLOATS;

#pragma unroll
        for (int ks = 0; ks < 4; ks++) {
            const int kb = ks * 8 + tg;
            uint32_t af[4][4];
#pragma unroll
            for (int i = 0; i < 4; i++) {
                const int r = wm * 64 + i * 16 + g;
                af[i][0] = rnd(sA[(r)     * SROW + kb]);
                af[i][1] = rnd(sA[(r + 8) * SROW + kb]);
                af[i][2] = rnd(sA[(r)     * SROW + kb + 4]);
                af[i][3] = rnd(sA[(r + 8) * SROW + kb + 4]);
            }
            uint32_t bf[8][2];
#pragma unroll
            for (int j = 0; j < 8; j++) {
                const int r = wn * 64 + j * 8 + g;
                bf[j][0] = rnd(sB[r * SROW + kb]);
                bf[j][1] = rnd(sB[r * SROW + kb + 4]);
            }
#pragma unroll
            for (int i = 0; i < 4; i++)
#pragma unroll
                for (int j = 0; j < 8; j++)
                    MMA_TF32(acc[i][j], af[i][0], af[i][1], af[i][2], af[i][3],
                             bf[j][0], bf[j][1]);
        }
    }

    // ---- epilogue: bias + ReLU, float2 stores ----
    float2 bv[8];
#pragma unroll
    for (int j = 0; j < 8; j++) {
        const int c = colBase + wn * 64 + j * 8 + 2 * tg;
        float2 b = *(const float2*)(bias1 + c);
        if (bias2) {
            float2 b2 = *(const float2*)(bias2 + c);
            b.x += b2.x; b.y += b2.y;
        }
        bv[j] = b;
    }
#pragma unroll
    for (int i = 0; i < 4; i++) {
        const int r0 = rowBase + wm * 64 + i * 16 + g;
#pragma unroll
        for (int j = 0; j < 8; j++) {
            const int c = colBase + wn * 64 + j * 8 + 2 * tg;
            float2 v0, v1;
            v0.x = fmaxf(acc[i][j][0] + bv[j].x, 0.0f);
            v0.y = fmaxf(acc[i][j][1] + bv[j].y, 0.0f);
            v1.x = fmaxf(acc[i][j][2] + bv[j].x, 0.0f);
            v1.y = fmaxf(acc[i][j][3] + bv[j].y, 0.0f);
            *(float2*)&C[(size_t)r0 * ldc + c]       = v0;
            *(float2*)&C[(size_t)(r0 + 8) * ldc + c] = v1;
        }
    }
}

extern "C" void kernel_launch(void* const* d_in, const int* in_sizes, int n_in,
                              void* d_out, int out_size)
{
    (void)in_sizes; (void)n_in; (void)out_size;
    const int B_ = 8192, DIN = 1024, H_ = 4096, DO_ = 1024;

    const float* X     = (const float*)d_in[0];
    const float* state = (const float*)d_in[1];
    const float* W_in  = (const float*)d_in[2];
    const float* b_in  = (const float*)d_in[3];
    const float* W_rec = (const float*)d_in[4];
    const float* b_rec = (const float*)d_in[5];
    const float* W_out = (const float*)d_in[6];
    const float* b_out = (const float*)d_in[7];

    float* out       = (float*)d_out;                     // [B, D_OUT]
    float* new_state = (float*)d_out + (size_t)B_ * DO_;  // [B, H]

    static int inited = 0;
    if (!inited) {
        cudaFuncSetAttribute(rnn_gemm_mma,
                             cudaFuncAttributeMaxDynamicSharedMemorySize, SMEM_BYTES);
        inited = 1;
    }

    // GEMM1+2 fused along K: new_state = ReLU(X@W_in^T + state@W_rec^T + b)
    {
        dim3 grid(H_ / BN, B_ / BM);   // (32, 64)
        rnn_gemm_mma<<<grid, 128, SMEM_BYTES>>>(
            X, DIN, W_in, DIN, DIN / BK,
            state, H_, W_rec, H_, H_ / BK,
            b_in, b_rec, new_state, H_);
    }
    // GEMM3: out = ReLU(new_state@W_out^T + b_out)
    {
        dim3 grid(DO_ / BN, B_ / BM);  // (8, 64)
        rnn_gemm_mma<<<grid, 128, SMEM_BYTES>>>(
            new_state, H_, W_out, H_, H_ / BK,
            nullptr, 0, nullptr, 0, 0,
            b_out, nullptr, out, DO_);
    }
}